// round 2
// baseline (speedup 1.0000x reference)
#include <cuda_runtime.h>
#include <cstdint>

// Problem dims (fixed by reference)
#define EMBED  512
#define CONVC  512
#define HID    1024
#define LABELS 128
#define M_TOTAL (32 * 1024)   // B*S = 32768

// Scratch for intermediates (allocation-free rule -> __device__ globals)
__device__ float g_h[(size_t)M_TOTAL * CONVC];  // 64 MB
__device__ float g_z[(size_t)M_TOTAL * HID];    // 128 MB

__device__ __forceinline__ uint32_t f2tf32(float x) {
    uint32_t y;
    asm("cvt.rna.tf32.f32 %0, %1;" : "=r"(y) : "f"(x));
    return y;
}

__device__ __forceinline__ void mma_tf32(float* c, const uint32_t* a, const uint32_t* b) {
    asm volatile(
        "mma.sync.aligned.m16n8k8.row.col.f32.tf32.tf32.f32 "
        "{%0,%1,%2,%3}, {%4,%5,%6,%7}, {%8,%9}, {%0,%1,%2,%3};\n"
        : "+f"(c[0]), "+f"(c[1]), "+f"(c[2]), "+f"(c[3])
        : "r"(a[0]), "r"(a[1]), "r"(a[2]), "r"(a[3]),
          "r"(b[0]), "r"(b[1]));
}

// Tiled tf32 GEMM: C[M,N] = act( A[M,K] * B + bias )
//   GATHER:   A rows come from emb_table[tok[m]]
//   B_KMAJOR: W is [N,K] (k contiguous, used directly as col-major B)
//             else W is [K,N] (n contiguous)
//   RELU:     apply relu in epilogue
// Tiles: BM=128, BN=64, BK=32; 256 threads = 8 warps (4 M x 2 N), warp tile 32x32.
template <int N, int K, bool GATHER, bool B_KMAJOR, bool RELU>
__global__ __launch_bounds__(256)
void gemm_tf32_kernel(const float* __restrict__ A,   // [M,K] or emb_table [VOCAB,K]
                      const int* __restrict__ tok,   // [M] when GATHER
                      const float* __restrict__ W,
                      const float* __restrict__ bias,
                      float* __restrict__ C) {
    constexpr int BM = 128, BN = 64, BK = 32;
    constexpr int APITCH = BK + 4;   // 36 floats -> conflict-free frag loads
    constexpr int BPITCH_K = BK + 4; // Bs[n][k] layout
    constexpr int BPITCH_N = BN + 4; // Bs[k][n] layout

    __shared__ uint32_t As[BM * APITCH];           // 18432 B
    __shared__ uint32_t Bs[BN * BPITCH_K];         // 9216 B (covers both layouts)
    __shared__ int stok[BM];

    const int tid  = threadIdx.x;
    const int warp = tid >> 5;
    const int lane = tid & 31;
    const int grp  = lane >> 2;   // 0..7
    const int tig  = lane & 3;    // 0..3
    const int warp_m = warp >> 1; // 0..3
    const int warp_n = warp & 1;  // 0..1

    const int bm = blockIdx.y * BM;
    const int bn = blockIdx.x * BN;

    if (GATHER) {
        if (tid < BM) stok[tid] = tok[bm + tid];
        __syncthreads();
    }

    float acc[2][4][4];
#pragma unroll
    for (int mi = 0; mi < 2; mi++)
#pragma unroll
        for (int ni = 0; ni < 4; ni++)
#pragma unroll
            for (int j = 0; j < 4; j++) acc[mi][ni][j] = 0.0f;

    for (int kt = 0; kt < K / BK; kt++) {
        const int k0 = kt * BK;

        // ---- Load A tile: 128x32 floats = 1024 float4, 4 per thread
#pragma unroll
        for (int i = 0; i < 4; i++) {
            int idx = tid + i * 256;
            int r = idx >> 3;
            int c4 = idx & 7;
            long arow;
            if (GATHER) arow = (long)stok[r] * K;
            else        arow = (long)(bm + r) * K;
            float4 v = *(const float4*)(A + arow + k0 + c4 * 4);
            uint32_t* dst = &As[r * APITCH + c4 * 4];
            dst[0] = f2tf32(v.x); dst[1] = f2tf32(v.y);
            dst[2] = f2tf32(v.z); dst[3] = f2tf32(v.w);
        }

        // ---- Load B tile: 64x32 floats = 512 float4, 2 per thread
        if (B_KMAJOR) {
#pragma unroll
            for (int i = 0; i < 2; i++) {
                int idx = tid + i * 256;
                int n = idx >> 3;
                int c4 = idx & 7;
                float4 v = *(const float4*)(W + (long)(bn + n) * K + k0 + c4 * 4);
                uint32_t* dst = &Bs[n * BPITCH_K + c4 * 4];
                dst[0] = f2tf32(v.x); dst[1] = f2tf32(v.y);
                dst[2] = f2tf32(v.z); dst[3] = f2tf32(v.w);
            }
        } else {
#pragma unroll
            for (int i = 0; i < 2; i++) {
                int idx = tid + i * 256;
                int kk = idx >> 4;
                int c4 = idx & 15;
                float4 v = *(const float4*)(W + (long)(k0 + kk) * N + bn + c4 * 4);
                uint32_t* dst = &Bs[kk * BPITCH_N + c4 * 4];
                dst[0] = f2tf32(v.x); dst[1] = f2tf32(v.y);
                dst[2] = f2tf32(v.z); dst[3] = f2tf32(v.w);
            }
        }
        __syncthreads();

        // ---- Compute: 4 k-steps of k=8
#pragma unroll
        for (int ks = 0; ks < 4; ks++) {
            const int kk = ks * 8;
            uint32_t a[2][4], b[4][2];
#pragma unroll
            for (int mi = 0; mi < 2; mi++) {
                int r = warp_m * 32 + mi * 16 + grp;
                a[mi][0] = As[r * APITCH + kk + tig];
                a[mi][1] = As[(r + 8) * APITCH + kk + tig];
                a[mi][2] = As[r * APITCH + kk + tig + 4];
                a[mi][3] = As[(r + 8) * APITCH + kk + tig + 4];
            }
#pragma unroll
            for (int ni = 0; ni < 4; ni++) {
                int n = warp_n * 32 + ni * 8 + grp;
                if (B_KMAJOR) {
                    b[ni][0] = Bs[n * BPITCH_K + kk + tig];
                    b[ni][1] = Bs[n * BPITCH_K + kk + tig + 4];
                } else {
                    b[ni][0] = Bs[(kk + tig) * BPITCH_N + n];
                    b[ni][1] = Bs[(kk + tig + 4) * BPITCH_N + n];
                }
            }
#pragma unroll
            for (int mi = 0; mi < 2; mi++)
#pragma unroll
                for (int ni = 0; ni < 4; ni++)
                    mma_tf32(acc[mi][ni], a[mi], b[ni]);
        }
        __syncthreads();
    }

    // ---- Epilogue: bias (+relu), write C
#pragma unroll
    for (int mi = 0; mi < 2; mi++) {
        const int m0 = bm + warp_m * 32 + mi * 16 + grp;
#pragma unroll
        for (int ni = 0; ni < 4; ni++) {
            const int n = bn + warp_n * 32 + ni * 8 + tig * 2;
            const float bv0 = bias[n];
            const float bv1 = bias[n + 1];
            float v0 = acc[mi][ni][0] + bv0;
            float v1 = acc[mi][ni][1] + bv1;
            float v2 = acc[mi][ni][2] + bv0;
            float v3 = acc[mi][ni][3] + bv1;
            if (RELU) {
                v0 = fmaxf(v0, 0.0f); v1 = fmaxf(v1, 0.0f);
                v2 = fmaxf(v2, 0.0f); v3 = fmaxf(v3, 0.0f);
            }
            *(float2*)(C + (long)m0 * N + n)       = make_float2(v0, v1);
            *(float2*)(C + (long)(m0 + 8) * N + n) = make_float2(v2, v3);
        }
    }
}

extern "C" void kernel_launch(void* const* d_in, const int* in_sizes, int n_in,
                              void* d_out, int out_size) {
    const int*   tok    = (const int*)d_in[0];
    const float* emb    = (const float*)d_in[1];
    const float* conv_w = (const float*)d_in[2];   // [CONVC, EMBED] (k-major)
    const float* conv_b = (const float*)d_in[3];
    const float* w1     = (const float*)d_in[4];   // [CONVC, HID]  (n-major)
    const float* b1     = (const float*)d_in[5];
    const float* w2     = (const float*)d_in[6];   // [HID, LABELS] (n-major)
    const float* b2     = (const float*)d_in[7];
    float* out = (float*)d_out;

    float *h_buf = nullptr, *z_buf = nullptr;
    cudaGetSymbolAddress((void**)&h_buf, g_h);
    cudaGetSymbolAddress((void**)&z_buf, g_z);

    // GEMM1: h = relu(emb[tok] @ conv_w^T + conv_b)   [32768, 512]
    gemm_tf32_kernel<CONVC, EMBED, true, true, true>
        <<<dim3(CONVC / 64, M_TOTAL / 128), 256>>>(emb, tok, conv_w, conv_b, h_buf);

    // GEMM2: z = relu(h @ dec_w1 + dec_b1)            [32768, 1024]
    gemm_tf32_kernel<HID, CONVC, false, false, true>
        <<<dim3(HID / 64, M_TOTAL / 128), 256>>>(h_buf, nullptr, w1, b1, z_buf);

    // GEMM3: out = z @ dec_w2 + dec_b2                [32768, 128]
    gemm_tf32_kernel<LABELS, HID, false, false, false>
        <<<dim3(LABELS / 64, M_TOTAL / 128), 256>>>(z_buf, nullptr, w2, b2, out);
}

// round 6
// speedup vs baseline: 1.5474x; 1.5474x over previous
#include <cuda_runtime.h>
#include <cstdint>

#define EMBED  512
#define CONVC  512
#define HID    1024
#define LABELS 128
#define M_TOTAL (32 * 1024)

// Scratch (allocation-free rule -> __device__ globals). All tf32-bit payloads in float containers.
__device__ float g_x[(size_t)M_TOTAL * EMBED];   // gathered+tf32 embeddings, 64 MB
__device__ float g_h[(size_t)M_TOTAL * CONVC];   // 64 MB (tf32 bits)
__device__ float g_z[(size_t)M_TOTAL * HID];     // 128 MB (tf32 bits)
__device__ float g_w0[(size_t)CONVC * EMBED];    // conv_w tf32 [N,K]
__device__ float g_w1t[(size_t)HID * CONVC];     // w1^T tf32 [1024,512]
__device__ float g_w2t[(size_t)LABELS * HID];    // w2^T tf32 [128,1024]

__device__ __forceinline__ uint32_t smem_u32(const void* p) {
    uint32_t a;
    asm("{ .reg .u64 t; cvta.to.shared.u64 t, %1; cvt.u32.u64 %0, t; }" : "=r"(a) : "l"(p));
    return a;
}
__device__ __forceinline__ uint32_t f2tf32(float x) {
    uint32_t y; asm("cvt.rna.tf32.f32 %0, %1;" : "=r"(y) : "f"(x)); return y;
}
__device__ __forceinline__ float tf32f(float x) { return __uint_as_float(f2tf32(x)); }

#define CP_ASYNC16(dst, src) \
    asm volatile("cp.async.cg.shared.global [%0], [%1], 16;" :: "r"(dst), "l"(src))
#define CP_COMMIT() asm volatile("cp.async.commit_group;" ::: "memory")
#define CP_WAIT2()  asm volatile("cp.async.wait_group 2;" ::: "memory")

__device__ __forceinline__ void mma_tf32(float* c, const uint32_t* a, const uint32_t* b) {
    asm volatile(
        "mma.sync.aligned.m16n8k8.row.col.f32.tf32.tf32.f32 "
        "{%0,%1,%2,%3}, {%4,%5,%6,%7}, {%8,%9}, {%0,%1,%2,%3};\n"
        : "+f"(c[0]), "+f"(c[1]), "+f"(c[2]), "+f"(c[3])
        : "r"(a[0]), "r"(a[1]), "r"(a[2]), "r"(a[3]), "r"(b[0]), "r"(b[1]));
}

// ---------------- pipelined tf32 GEMM ----------------
// C[M, N_TOTAL] = act(A[M,K] @ Wt[N,K]^T + bias). A, Wt already hold tf32 bits.
// BM=256, BN=128, BK=32. 8 warps (4x2), warp tile 64x64. 3-stage cp.async ring.
template <int N_TOTAL, int K, bool RELU, bool CVT_OUT>
__global__ __launch_bounds__(256, 1)
void gemm_pipe(const float* __restrict__ A, const float* __restrict__ Wt,
               const float* __restrict__ bias, float* __restrict__ C) {
    constexpr int BM = 256, BN = 128, BK = 32;
    constexpr int KCH = K / BK;
    constexpr int PITCH = 36;                      // floats per row (bank-conflict-free)
    constexpr int A_BYTES = BM * PITCH * 4;        // 36864
    constexpr int B_BYTES = BN * PITCH * 4;        // 18432
    constexpr int STAGE = A_BYTES + B_BYTES;       // 55296

    extern __shared__ char smem[];
    const uint32_t sb = smem_u32(smem);

    const int tid  = threadIdx.x;
    const int warp = tid >> 5, lane = tid & 31;
    const int grp  = lane >> 2, tig = lane & 3;
    const int wm   = warp >> 1, wn = warp & 1;

    const int bm = blockIdx.y * BM;
    const int bn = blockIdx.x * BN;

    // stage issue: A tile 256x32 (8 chunks/thread), B tile 128x32 (4 chunks/thread)
    auto issue = [&](int s, int kt) {
        const int k0 = kt * BK;
        const uint32_t ab = sb + s * STAGE;
        const uint32_t bb = ab + A_BYTES;
#pragma unroll
        for (int i = 0; i < 8; i++) {
            int idx = tid + i * 256;
            int r = idx >> 3, c4 = idx & 7;
            CP_ASYNC16(ab + (uint32_t)(r * PITCH * 4 + c4 * 16),
                       A + (size_t)(bm + r) * K + k0 + c4 * 4);
        }
#pragma unroll
        for (int i = 0; i < 4; i++) {
            int idx = tid + i * 256;
            int r = idx >> 3, c4 = idx & 7;
            CP_ASYNC16(bb + (uint32_t)(r * PITCH * 4 + c4 * 16),
                       Wt + (size_t)(bn + r) * K + k0 + c4 * 4);
        }
    };

    float acc[4][8][4];
#pragma unroll
    for (int mi = 0; mi < 4; mi++)
#pragma unroll
        for (int ni = 0; ni < 8; ni++)
#pragma unroll
            for (int j = 0; j < 4; j++) acc[mi][ni][j] = 0.0f;

    issue(0, 0); CP_COMMIT();
    issue(1, 1); CP_COMMIT();

    for (int kt = 0; kt < KCH; kt++) {
        const int s = kt % 3;
        if (kt + 2 < KCH) issue((kt + 2) % 3, kt + 2);
        CP_COMMIT();
        CP_WAIT2();
        __syncthreads();

        const uint32_t* As = (const uint32_t*)(smem + s * STAGE);
        const uint32_t* Bs = (const uint32_t*)(smem + s * STAGE + A_BYTES);
#pragma unroll
        for (int ks = 0; ks < 4; ks++) {
            const int kk = ks * 8;
            uint32_t a[4][4], b[8][2];
#pragma unroll
            for (int mi = 0; mi < 4; mi++) {
                int r = wm * 64 + mi * 16 + grp;
                a[mi][0] = As[r * PITCH + kk + tig];
                a[mi][1] = As[(r + 8) * PITCH + kk + tig];
                a[mi][2] = As[r * PITCH + kk + tig + 4];
                a[mi][3] = As[(r + 8) * PITCH + kk + tig + 4];
            }
#pragma unroll
            for (int ni = 0; ni < 8; ni++) {
                int n = wn * 64 + ni * 8 + grp;
                b[ni][0] = Bs[n * PITCH + kk + tig];
                b[ni][1] = Bs[n * PITCH + kk + tig + 4];
            }
#pragma unroll
            for (int mi = 0; mi < 4; mi++)
#pragma unroll
                for (int ni = 0; ni < 8; ni++)
                    mma_tf32(acc[mi][ni], a[mi], b[ni]);
        }
        __syncthreads();
    }

    // Epilogue: bias (+relu) (+tf32 re-quant for chained GEMMs)
#pragma unroll
    for (int ni = 0; ni < 8; ni++) {
        const int n = bn + wn * 64 + ni * 8 + tig * 2;
        const float bv0 = __ldg(&bias[n]);
        const float bv1 = __ldg(&bias[n + 1]);
#pragma unroll
        for (int mi = 0; mi < 4; mi++) {
            const int m0 = bm + wm * 64 + mi * 16 + grp;
            float v0 = acc[mi][ni][0] + bv0;
            float v1 = acc[mi][ni][1] + bv1;
            float v2 = acc[mi][ni][2] + bv0;
            float v3 = acc[mi][ni][3] + bv1;
            if (RELU) {
                v0 = fmaxf(v0, 0.0f); v1 = fmaxf(v1, 0.0f);
                v2 = fmaxf(v2, 0.0f); v3 = fmaxf(v3, 0.0f);
            }
            if (CVT_OUT) {
                v0 = tf32f(v0); v1 = tf32f(v1); v2 = tf32f(v2); v3 = tf32f(v3);
            }
            *(float2*)(C + (size_t)m0 * N_TOTAL + n)       = make_float2(v0, v1);
            *(float2*)(C + (size_t)(m0 + 8) * N_TOTAL + n) = make_float2(v2, v3);
        }
    }
}

// ---------------- prep kernels ----------------
// Gather embedding rows + convert to tf32: x[m, :] = tf32(emb[tok[m], :])
__global__ __launch_bounds__(256)
void gather_cvt_kernel(const int* __restrict__ tok, const float* __restrict__ emb,
                       float* __restrict__ out) {
    const int i4 = blockIdx.x * 256 + threadIdx.x;          // one float4 each
    const int row = i4 >> 7;                                 // EMBED/4 = 128
    const int c   = (i4 & 127) << 2;
    const float4 v = *(const float4*)(emb + (size_t)tok[row] * EMBED + c);
    float4 o = make_float4(tf32f(v.x), tf32f(v.y), tf32f(v.z), tf32f(v.w));
    *(float4*)(out + (size_t)row * EMBED + c) = o;
}

// Elementwise tf32 convert (conv_w is already [N,K])
__global__ __launch_bounds__(256)
void cvt_kernel(const float* __restrict__ in, float* __restrict__ out) {
    const int i4 = blockIdx.x * 256 + threadIdx.x;
    const float4 v = *(const float4*)(in + (size_t)i4 * 4);
    *(float4*)(out + (size_t)i4 * 4) = make_float4(tf32f(v.x), tf32f(v.y), tf32f(v.z), tf32f(v.w));
}

// Transpose [R,C] -> [C,R] with tf32 convert
__global__ void transpose_cvt_kernel(const float* __restrict__ in, float* __restrict__ out,
                                     int R, int Ccols) {
    __shared__ float t[32][33];
    int bx = blockIdx.x * 32, by = blockIdx.y * 32;
    int x = bx + threadIdx.x;
#pragma unroll
    for (int j = 0; j < 32; j += 8) {
        int y = by + threadIdx.y + j;
        t[threadIdx.y + j][threadIdx.x] = in[(size_t)y * Ccols + x];
    }
    __syncthreads();
    x = by + threadIdx.x;
#pragma unroll
    for (int j = 0; j < 32; j += 8) {
        int y = bx + threadIdx.y + j;
        out[(size_t)y * R + x] = tf32f(t[threadIdx.x][threadIdx.y + j]);
    }
}

extern "C" void kernel_launch(void* const* d_in, const int* in_sizes, int n_in,
                              void* d_out, int out_size) {
    const int*   tok    = (const int*)d_in[0];
    const float* emb    = (const float*)d_in[1];
    const float* conv_w = (const float*)d_in[2];   // [CONVC, EMBED] = [N,K]
    const float* conv_b = (const float*)d_in[3];
    const float* w1     = (const float*)d_in[4];   // [CONVC, HID]
    const float* b1     = (const float*)d_in[5];
    const float* w2     = (const float*)d_in[6];   // [HID, LABELS]
    const float* b2     = (const float*)d_in[7];
    float* out = (float*)d_out;

    float *x_buf, *h_buf, *z_buf, *w0, *w1t, *w2t;
    cudaGetSymbolAddress((void**)&x_buf, g_x);
    cudaGetSymbolAddress((void**)&h_buf, g_h);
    cudaGetSymbolAddress((void**)&z_buf, g_z);
    cudaGetSymbolAddress((void**)&w0,  g_w0);
    cudaGetSymbolAddress((void**)&w1t, g_w1t);
    cudaGetSymbolAddress((void**)&w2t, g_w2t);

    constexpr int SMEM = 3 * (256 * 36 * 4 + 128 * 36 * 4);   // 165888
    cudaFuncSetAttribute(gemm_pipe<CONVC, EMBED, true,  true>,
                         cudaFuncAttributeMaxDynamicSharedMemorySize, SMEM);
    cudaFuncSetAttribute(gemm_pipe<HID, CONVC, true,  true>,
                         cudaFuncAttributeMaxDynamicSharedMemorySize, SMEM);
    cudaFuncSetAttribute(gemm_pipe<LABELS, HID, false, false>,
                         cudaFuncAttributeMaxDynamicSharedMemorySize, SMEM);

    // Prep: gather+cvt activations, cvt/transpose weights (bandwidth-trivial)
    gather_cvt_kernel<<<(M_TOTAL * EMBED / 4) / 256, 256>>>(tok, emb, x_buf);
    cvt_kernel<<<(CONVC * EMBED / 4) / 256, 256>>>(conv_w, w0);
    transpose_cvt_kernel<<<dim3(HID / 32, CONVC / 32), dim3(32, 8)>>>(w1, w1t, CONVC, HID);
    transpose_cvt_kernel<<<dim3(LABELS / 32, HID / 32), dim3(32, 8)>>>(w2, w2t, HID, LABELS);

    // GEMM1: h = tf32(relu(x @ conv_w^T + conv_b))    [32768, 512]
    gemm_pipe<CONVC, EMBED, true, true>
        <<<dim3(CONVC / 128, M_TOTAL / 256), 256, SMEM>>>(x_buf, w0, conv_b, h_buf);
    // GEMM2: z = tf32(relu(h @ w1 + b1))              [32768, 1024]
    gemm_pipe<HID, CONVC, true, true>
        <<<dim3(HID / 128, M_TOTAL / 256), 256, SMEM>>>(h_buf, w1t, b1, z_buf);
    // GEMM3: out = z @ w2 + b2                        [32768, 128]
    gemm_pipe<LABELS, HID, false, false>
        <<<dim3(LABELS / 128, M_TOTAL / 256), 256, SMEM>>>(z_buf, w2t, b2, out);
}